// round 10
// baseline (speedup 1.0000x reference)
#include <cuda_runtime.h>
#include <math.h>

#define Td 32
#define Bd 8
#define Id 512
#define Hd 512
#define H3 1536
#define NBLK 256

// ---- output layout (concatenated tuple: v, h, dU, te, tE, outs) ----
#define OFF_V    0
#define OFF_H    4096
#define OFF_DU   8192
#define OFF_TE   2105344
#define OFF_TEE  2109440
#define OFF_OUTS 4206592

// ---- scratch (device globals; no allocation allowed) ----
__device__ float g_xproj[Td * Bd * H3]; // 1.5 MB (middle third unused)
__device__ float g_hbuf[2][Bd * Hd];    // ping-pong hidden state
__device__ unsigned g_count = 0;
__device__ unsigned g_flag[16 * 32];    // 16 broadcast flags, 128B apart
// gate accumulators: 4 rotating buffers x 32 gates, each padded to 256B
// so the 32 concurrent atomic targets spread across many L2 slices.
#define GPAD 64
__device__ float g_gates[4][32 * GPAD];

// ============================================================
// xproj for z and dv chunks only (r chunk is dead in the reference).
// ============================================================
__global__ void __launch_bounds__(256) k_xproj(const float* __restrict__ x,
                                               const float* __restrict__ x2h_v,
                                               const float* __restrict__ x2h_g,
                                               const float* __restrict__ x2h_b) {
    __shared__ float xs[8 * 512]; // 16 KB
    int n = (blockIdx.x < 2) ? (blockIdx.x * 256 + threadIdx.x)
                             : (1024 + (blockIdx.x - 2) * 256 + threadIdx.x);
    int m0 = blockIdx.y * 8;
    for (int idx = threadIdx.x; idx < 8 * 512; idx += 256)
        xs[idx] = x[(m0 + (idx >> 9)) * 512 + (idx & 511)];
    __syncthreads();
    float acc[8];
#pragma unroll
    for (int m = 0; m < 8; m++) acc[m] = 0.f;
    float ss = 0.f;
    const float4* wrow4 = (const float4*)(x2h_v + n * 512);
#pragma unroll 2
    for (int c = 0; c < 128; c++) {
        float4 w4 = wrow4[c];
        ss = fmaf(w4.x, w4.x, ss); ss = fmaf(w4.y, w4.y, ss);
        ss = fmaf(w4.z, w4.z, ss); ss = fmaf(w4.w, w4.w, ss);
#pragma unroll
        for (int m = 0; m < 8; m++) {
            float4 x4 = ((const float4*)(xs + m * 512))[c];
            acc[m] = fmaf(w4.x, x4.x, acc[m]);
            acc[m] = fmaf(w4.y, x4.y, acc[m]);
            acc[m] = fmaf(w4.z, x4.z, acc[m]);
            acc[m] = fmaf(w4.w, x4.w, acc[m]);
        }
    }
    float sc = x2h_g[n] * rsqrtf(ss);
    float bb = x2h_b[n];
#pragma unroll
    for (int m = 0; m < 8; m++)
        g_xproj[(m0 + m) * H3 + n] = fmaf(acc[m], sc, bb);
}

// ============================================================
// Grid-wide software barrier (NBLK participants).
// ============================================================
__device__ __forceinline__ void grid_bar(unsigned &lgen, int fidx) {
    __syncthreads();
    __threadfence();
    if (threadIdx.x == 0) {
        unsigned a = atomicAdd(&g_count, 1u);
        if (a == NBLK - 1u) {
            g_count = 0u;
            __threadfence();
#pragma unroll
            for (int f = 0; f < 16; f++)
                ((volatile unsigned*)g_flag)[f * 32] = lgen + 1u;
        } else {
            volatile unsigned* vf = &g_flag[fidx * 32];
            while (*vf == lgen) { }
        }
        lgen += 1u;
    }
    __syncthreads();
}

__device__ __forceinline__ float sigf(float x) { return 1.f / (1.f + __expf(-x)); }
__device__ __forceinline__ float sshr(float y) {
    return (y > 0.5f) ? y - 0.5f : ((y < -0.5f) ? y + 0.5f : 0.f);
}

// ============================================================
// Persistent scan: 256 blocks own 2 rows each (iA=blk, iB=blk+256).
// Row A dU/tE in SMEM, row B dU/tE in REGISTERS. hn double-buffered
// in SMEM; staging loads overlapped with the te update.
// ============================================================
__global__ void __launch_bounds__(256, 2) k_scan(
    const float* __restrict__ h0, const float* __restrict__ v0,
    const float* __restrict__ dU0, const float* __restrict__ te0,
    const float* __restrict__ tE0, const float* __restrict__ alpha,
    const float* __restrict__ h2h_v, const float* __restrict__ h2h_g,
    const float* __restrict__ h2h_b, const float* __restrict__ h2mod_w,
    const float* __restrict__ h2mod_b, const float* __restrict__ modU_w,
    const float* __restrict__ modU_b, float* __restrict__ out)
{
    extern __shared__ float sm[];
    float* s_hn0 = sm;             // 4096 (h buffer 0)
    float* s_hn1 = s_hn0 + 4096;   // 4096 (h buffer 1)
    float* sdU   = s_hn1 + 4096;   // 4096 (row A)
    float* stE   = sdU + 4096;     // 4096 (row A)
    float* s_wzA = stE + 4096;     // 512
    float* s_wdA = s_wzA + 512;    // 512
    float* s_wzB = s_wdA + 512;    // 512
    float* s_wdB = s_wzB + 512;    // 512
    // total 18432 floats = 73728 B

    __shared__ float sv[16], s_dvacc[16];
    __shared__ float s_hniA[8], s_hniB[8], s_teiA[8], s_teiB[8];
    __shared__ float s_g[32];
    __shared__ float s_red[8][16];
    __shared__ float s_sc[6];
    __shared__ float s_mw8[8], s_mb[4];

    const int iA = blockIdx.x, iB = iA + 256;
    const int tid = threadIdx.x;
    const int wb = tid >> 5, lane = tid & 31;
    const int fidx = blockIdx.x & 15;
    unsigned lgen = ((volatile unsigned*)g_flag)[fidx * 32];

    if (tid < 8) s_mw8[tid] = h2mod_w[(tid & 3) * 512 + ((tid < 4) ? iA : iB)];
    if (tid < 4) s_mb[tid] = h2mod_b[tid];
    const float bzA = h2h_b[iA], bdA = h2h_b[2 * Hd + iA];
    const float bzB = h2h_b[iB], bdB = h2h_b[2 * Hd + iB];

    // ---- inline weight-norm: 6 h2h rows (z/r/d for iA and iB) ----
    float2 vzA = ((const float2*)(h2h_v + iA * Hd))[tid];
    float2 vrA = ((const float2*)(h2h_v + (Hd + iA) * Hd))[tid];
    float2 vdA = ((const float2*)(h2h_v + (2 * Hd + iA) * Hd))[tid];
    float2 vzB = ((const float2*)(h2h_v + iB * Hd))[tid];
    float2 vrB = ((const float2*)(h2h_v + (Hd + iB) * Hd))[tid];
    float2 vdB = ((const float2*)(h2h_v + (2 * Hd + iB) * Hd))[tid];
    {
        float s0 = vzA.x * vzA.x + vzA.y * vzA.y;
        float s1 = vrA.x * vrA.x + vrA.y * vrA.y;
        float s2 = vdA.x * vdA.x + vdA.y * vdA.y;
        float s3 = vzB.x * vzB.x + vzB.y * vzB.y;
        float s4 = vrB.x * vrB.x + vrB.y * vrB.y;
        float s5 = vdB.x * vdB.x + vdB.y * vdB.y;
#pragma unroll
        for (int o = 16; o; o >>= 1) {
            s0 += __shfl_xor_sync(0xffffffffu, s0, o);
            s1 += __shfl_xor_sync(0xffffffffu, s1, o);
            s2 += __shfl_xor_sync(0xffffffffu, s2, o);
            s3 += __shfl_xor_sync(0xffffffffu, s3, o);
            s4 += __shfl_xor_sync(0xffffffffu, s4, o);
            s5 += __shfl_xor_sync(0xffffffffu, s5, o);
        }
        if (lane == 0) {
            s_red[wb][0] = s0; s_red[wb][1] = s1; s_red[wb][2] = s2;
            s_red[wb][3] = s3; s_red[wb][4] = s4; s_red[wb][5] = s5;
        }
    }
    __syncthreads();
    if (tid < 6) {
        float s = 0.f;
#pragma unroll
        for (int w2 = 0; w2 < 8; w2++) s += s_red[w2][tid];
        int col = (tid < 3) ? iA : iB;
        int row = (tid % 3) * Hd + col;
        s_sc[tid] = h2h_g[row] * rsqrtf(s);
    }
    __syncthreads();

    // per-row constants into registers (+ wz/wd into smem)
    float2 alA, alB, wvA, wvB, bvA, bvB, loA, loB, upA, upB;
    {
        ((float2*)s_wzA)[tid] = make_float2(vzA.x * s_sc[0], vzA.y * s_sc[0]);
        ((float2*)s_wdA)[tid] = make_float2(vdA.x * s_sc[2], vdA.y * s_sc[2]);
        ((float2*)s_wzB)[tid] = make_float2(vzB.x * s_sc[3], vzB.y * s_sc[3]);
        ((float2*)s_wdB)[tid] = make_float2(vdB.x * s_sc[5], vdB.y * s_sc[5]);
        alA = ((const float2*)(alpha + iA * Hd))[tid];
        alB = ((const float2*)(alpha + iB * Hd))[tid];
        wvA = ((const float2*)(modU_w + iA * Hd))[tid];
        wvB = ((const float2*)(modU_w + iB * Hd))[tid];
        bvA = ((const float2*)(modU_b + iA * Hd))[tid];
        bvB = ((const float2*)(modU_b + iB * Hd))[tid];
        float wrx = vrA.x * s_sc[1], wry = vrA.y * s_sc[1];
        float ax = alA.x + 1e-5f, ay = alA.y + 1e-5f;
        upA = make_float2(fmaxf(1.f - wrx, 0.f) / ax, fmaxf(1.f - wry, 0.f) / ay);
        loA = make_float2(-fmaxf(1.f + wrx, 0.f) / ax, -fmaxf(1.f + wry, 0.f) / ay);
        wrx = vrB.x * s_sc[4]; wry = vrB.y * s_sc[4];
        ax = alB.x + 1e-5f; ay = alB.y + 1e-5f;
        upB = make_float2(fmaxf(1.f - wrx, 0.f) / ax, fmaxf(1.f - wry, 0.f) / ay);
        loB = make_float2(-fmaxf(1.f + wrx, 0.f) / ax, -fmaxf(1.f + wry, 0.f) / ay);
    }

    // ---- stage h0 and init state ----
    for (int idx = tid; idx < 1024; idx += 256)
        ((float4*)s_hn0)[idx] = ((const float4*)h0)[idx];

    float2 te[8], dUB[8], tEB[8];
#pragma unroll
    for (int u = 0; u < 8; u++) {
        float2 dA = ((const float2*)(dU0 + (u * Hd + iA) * Hd))[tid];
        ((float2*)sdU)[u * 256 + tid] = dA;
        ((float2*)stE)[u * 256 + tid] = ((const float2*)(tE0 + (u * Hd + iA) * Hd))[tid];
        dUB[u] = ((const float2*)(dU0 + (u * Hd + iB) * Hd))[tid];
        tEB[u] = ((const float2*)(tE0 + (u * Hd + iB) * Hd))[tid];
        te[u] = ((const float2*)(te0 + u * Hd))[tid];
        float2 h2 = ((const float2*)(h0 + u * Hd))[tid];
        float accA = alA.x * dA.x * h2.x + alA.y * dA.y * h2.y;
        float accB = alB.x * dUB[u].x * h2.x + alB.y * dUB[u].y * h2.y;
#pragma unroll
        for (int o = 16; o; o >>= 1) {
            accA += __shfl_xor_sync(0xffffffffu, accA, o);
            accB += __shfl_xor_sync(0xffffffffu, accB, o);
        }
        if (lane == 0) { s_red[wb][u] = accA; s_red[wb][8 + u] = accB; }
    }
    if (tid < 16) sv[tid] = v0[(tid & 7) * Hd + ((tid < 8) ? iA : iB)];
    __syncthreads();
    if (tid < 16) {
        float s = 0.f;
#pragma unroll
        for (int w2 = 0; w2 < 8; w2++) s += s_red[w2][tid];
        s_dvacc[tid] = s;
    }
    __syncthreads();

    for (int t = 0; t < Td; t++) {
        float* hn_buf = g_hbuf[t & 1];
        float* s_cur = (t & 1) ? s_hn1 : s_hn0;   // holds h_t
        float* s_nxt = (t & 1) ? s_hn0 : s_hn1;   // will hold h_{t+1}

        // ---- phase A: hn for rows iA,iB, batch wb (warp = batch) ----
        {
            float xpzA = 0.f, xpdA = 0.f, xpzB = 0.f, xpdB = 0.f;
            float dvA = 0.f, dvB = 0.f, voA = 0.f, voB = 0.f;
            if (lane == 0) {
                const float* xp = g_xproj + (t * Bd + wb) * H3;
                xpzA = __ldcg(xp + iA); xpdA = __ldcg(xp + 2 * Hd + iA);
                xpzB = __ldcg(xp + iB); xpdB = __ldcg(xp + 2 * Hd + iB);
                dvA = s_dvacc[wb]; dvB = s_dvacc[8 + wb];
                voA = sv[wb]; voB = sv[8 + wb];
            }
            const float4* hb4 = (const float4*)(s_cur + wb * Hd);
            float azA = 0.f, adA = 0.f, azB = 0.f, adB = 0.f;
#pragma unroll
            for (int it = 0; it < 4; it++) {
                float4 h4 = hb4[lane + 32 * it];
                float4 a4 = ((const float4*)s_wzA)[lane + 32 * it];
                float4 c4 = ((const float4*)s_wdA)[lane + 32 * it];
                float4 e4 = ((const float4*)s_wzB)[lane + 32 * it];
                float4 f4 = ((const float4*)s_wdB)[lane + 32 * it];
                azA = fmaf(a4.x, h4.x, azA); azA = fmaf(a4.y, h4.y, azA);
                azA = fmaf(a4.z, h4.z, azA); azA = fmaf(a4.w, h4.w, azA);
                adA = fmaf(c4.x, h4.x, adA); adA = fmaf(c4.y, h4.y, adA);
                adA = fmaf(c4.z, h4.z, adA); adA = fmaf(c4.w, h4.w, adA);
                azB = fmaf(e4.x, h4.x, azB); azB = fmaf(e4.y, h4.y, azB);
                azB = fmaf(e4.z, h4.z, azB); azB = fmaf(e4.w, h4.w, azB);
                adB = fmaf(f4.x, h4.x, adB); adB = fmaf(f4.y, h4.y, adB);
                adB = fmaf(f4.z, h4.z, adB); adB = fmaf(f4.w, h4.w, adB);
            }
#pragma unroll
            for (int o = 16; o; o >>= 1) {
                azA += __shfl_xor_sync(0xffffffffu, azA, o);
                adA += __shfl_xor_sync(0xffffffffu, adA, o);
                azB += __shfl_xor_sync(0xffffffffu, azB, o);
                adB += __shfl_xor_sync(0xffffffffu, adB, o);
            }
            if (lane == 0) {
                float z  = sigf(xpzA + azA + bzA);
                float dv = xpdA + adA + bdA + dvA;
                float vn = voA + z * (dv - voA);
                sv[wb] = vn;
                float hn = fmaxf(vn, 0.f);
                s_hniA[wb] = hn;
                hn_buf[wb * Hd + iA] = hn;
                __stcg(out + OFF_OUTS + (t * Bd + wb) * Hd + iA, hn);
                z  = sigf(xpzB + azB + bzB);
                dv = xpdB + adB + bdB + dvB;
                vn = voB + z * (dv - voB);
                sv[8 + wb] = vn;
                hn = fmaxf(vn, 0.f);
                s_hniB[wb] = hn;
                hn_buf[wb * Hd + iB] = hn;
                __stcg(out + OFF_OUTS + (t * Bd + wb) * Hd + iB, hn);
            }
        }
        __syncthreads();
        // combined gate contribution for both rows: one atomic per gate slot
        if (tid < 32) {
            int bb = tid >> 2, g = tid & 3;
            float v = s_mw8[g] * s_hniA[bb] + s_mw8[4 + g] * s_hniB[bb];
            atomicAdd(&g_gates[t & 3][tid * GPAD], v);
        }

        grid_bar(lgen, fidx);

        // ---- gates: read finished sums, apply activations ----
        if (tid < 32) {
            float v = __ldcg(&g_gates[t & 3][tid * GPAD]) + s_mb[tid & 3];
            s_g[tid] = ((tid & 3) == 3) ? fmaxf(v, 0.f) : sigf(v);
        }
        if (iA == 0 && tid >= 64 && tid < 96)
            g_gates[(t + 2) & 3][(tid - 64) * GPAD] = 0.f;

        // ---- issue staging loads of NEW hn (hide L2 latency) ----
        float4 stg[4];
#pragma unroll
        for (int k = 0; k < 4; k++)
            stg[k] = __ldcg((const float4*)hn_buf + tid + 256 * k);

        __syncthreads();   // s_g ready

        // ---- te update (uses OLD h still in s_cur) ----
#pragma unroll
        for (int u = 0; u < 8; u++) {
            float taue = s_g[u * 4 + 0];
            float2 h2 = ((const float2*)s_cur)[u * 256 + tid];
            te[u].x += taue * (h2.x - te[u].x);
            te[u].y += taue * (h2.y - te[u].y);
        }
        if (tid == (iA >> 1)) {
#pragma unroll
            for (int u = 0; u < 8; u++)
                s_teiA[u] = (iA & 1) ? te[u].y : te[u].x;
        }
        if (tid == (iB >> 1)) {
#pragma unroll
            for (int u = 0; u < 8; u++)
                s_teiB[u] = (iB & 1) ? te[u].y : te[u].x;
        }
        // ---- complete staging into s_nxt ----
#pragma unroll
        for (int k = 0; k < 4; k++)
            ((float4*)s_nxt)[tid + 256 * k] = stg[k];
        __syncthreads();   // s_nxt + s_tei ready

        // ---- main state update (rows A smem, B regs) + fused matvec ----
#pragma unroll
        for (int u = 0; u < 8; u++) {
            float2 hnj = ((const float2*)s_nxt)[u * 256 + tid];
            float tauE = s_g[u * 4 + 1], tauU = s_g[u * 4 + 2], mU = s_g[u * 4 + 3];
            float2 tn = te[u];
            // row A
            float hni = s_hniA[u], tei = s_teiA[u];
            float ox = hni * tn.x - tei * hnj.x;
            float oy = hni * tn.y - tei * hnj.y;
            float2 E = ((float2*)stE)[u * 256 + tid];
            E.x += tauE * (ox - E.x);
            E.y += tauE * (oy - E.y);
            ((float2*)stE)[u * 256 + tid] = E;
            float2 D = ((float2*)sdU)[u * 256 + tid];
            D.x += tauU * (sshr(fmaf(mU, wvA.x, bvA.x)) * E.x - D.x);
            D.y += tauU * (sshr(fmaf(mU, wvA.y, bvA.y)) * E.y - D.y);
            D.x = fminf(fmaxf(D.x, loA.x), upA.x);
            D.y = fminf(fmaxf(D.y, loA.y), upA.y);
            ((float2*)sdU)[u * 256 + tid] = D;
            float accA = alA.x * D.x * hnj.x + alA.y * D.y * hnj.y;
            // row B (registers)
            hni = s_hniB[u]; tei = s_teiB[u];
            ox = hni * tn.x - tei * hnj.x;
            oy = hni * tn.y - tei * hnj.y;
            tEB[u].x += tauE * (ox - tEB[u].x);
            tEB[u].y += tauE * (oy - tEB[u].y);
            dUB[u].x += tauU * (sshr(fmaf(mU, wvB.x, bvB.x)) * tEB[u].x - dUB[u].x);
            dUB[u].y += tauU * (sshr(fmaf(mU, wvB.y, bvB.y)) * tEB[u].y - dUB[u].y);
            dUB[u].x = fminf(fmaxf(dUB[u].x, loB.x), upB.x);
            dUB[u].y = fminf(fmaxf(dUB[u].y, loB.y), upB.y);
            float accB = alB.x * dUB[u].x * hnj.x + alB.y * dUB[u].y * hnj.y;
#pragma unroll
            for (int o = 16; o; o >>= 1) {
                accA += __shfl_xor_sync(0xffffffffu, accA, o);
                accB += __shfl_xor_sync(0xffffffffu, accB, o);
            }
            if (lane == 0) { s_red[wb][u] = accA; s_red[wb][8 + u] = accB; }
        }
        __syncthreads();
        if (tid < 16) {
            float s = 0.f;
#pragma unroll
            for (int w2 = 0; w2 < 8; w2++) s += s_red[w2][tid];
            s_dvacc[tid] = s;
        }
        __syncthreads();
    }

    // ---- epilogue: dump final state ----
    if (tid < 16) {
        int b = tid & 7, col = (tid < 8) ? iA : iB;
        out[OFF_V + b * Hd + col] = sv[tid];
        out[OFF_H + b * Hd + col] = (tid < 8) ? s_hniA[b] : s_hniB[b];
    }
#pragma unroll
    for (int u = 0; u < 8; u++) {
        ((float2*)(out + OFF_DU  + (u * Hd + iA) * Hd))[tid] = ((float2*)sdU)[u * 256 + tid];
        ((float2*)(out + OFF_TEE + (u * Hd + iA) * Hd))[tid] = ((float2*)stE)[u * 256 + tid];
        ((float2*)(out + OFF_DU  + (u * Hd + iB) * Hd))[tid] = dUB[u];
        ((float2*)(out + OFF_TEE + (u * Hd + iB) * Hd))[tid] = tEB[u];
    }
    if (iA == 0) {
#pragma unroll
        for (int u = 0; u < 8; u++)
            ((float2*)(out + OFF_TE + u * Hd))[tid] = te[u];
    }
}

extern "C" void kernel_launch(void* const* d_in, const int* in_sizes, int n_in,
                              void* d_out, int out_size) {
    const float* x       = (const float*)d_in[0];
    const float* h0      = (const float*)d_in[1];
    const float* v0      = (const float*)d_in[2];
    const float* dU0     = (const float*)d_in[3];
    const float* te0     = (const float*)d_in[4];
    const float* tE0     = (const float*)d_in[5];
    const float* x2h_v   = (const float*)d_in[6];
    const float* x2h_g   = (const float*)d_in[7];
    const float* x2h_b   = (const float*)d_in[8];
    const float* h2h_v   = (const float*)d_in[9];
    const float* h2h_g   = (const float*)d_in[10];
    const float* h2h_b   = (const float*)d_in[11];
    const float* alpha   = (const float*)d_in[12];
    const float* h2mod_w = (const float*)d_in[13];
    const float* h2mod_b = (const float*)d_in[14];
    const float* modU_w  = (const float*)d_in[15];
    const float* modU_b  = (const float*)d_in[16];
    float* out = (float*)d_out;

    const int scan_smem = 18432 * sizeof(float); // 73728 B
    cudaFuncSetAttribute(k_scan, cudaFuncAttributeMaxDynamicSharedMemorySize, scan_smem);

    k_xproj<<<dim3(4, 32), 256>>>(x, x2h_v, x2h_g, x2h_b);
    k_scan<<<NBLK, 256, scan_smem>>>(h0, v0, dU0, te0, tE0, alpha,
                                     h2h_v, h2h_g, h2h_b,
                                     h2mod_w, h2mod_b, modU_w, modU_b, out);
}

// round 11
// speedup vs baseline: 1.2876x; 1.2876x over previous
#include <cuda_runtime.h>
#include <math.h>

#define Td 32
#define Bd 8
#define Id 512
#define Hd 512
#define H3 1536
#define NBLK 256

// ---- output layout (concatenated tuple: v, h, dU, te, tE, outs) ----
#define OFF_V    0
#define OFF_H    4096
#define OFF_DU   8192
#define OFF_TE   2105344
#define OFF_TEE  2109440
#define OFF_OUTS 4206592

// ---- scratch (device globals; no allocation allowed) ----
__device__ float g_xproj[Td * Bd * H3]; // 1.5 MB (middle third unused)
__device__ float g_hbuf[2][Bd * Hd];    // ping-pong hidden state
__device__ unsigned g_count = 0;
__device__ unsigned g_flag[16 * 32];    // 16 broadcast flags, 128B apart
__device__ float g_gates[4][32];        // rotating gate accumulators [t&3][b*4+g]

// ---- cp.async helpers (LDGSTS; no destination registers) ----
__device__ __forceinline__ void cp_async16(float* smem_dst, const float* gsrc) {
    unsigned sa = (unsigned)__cvta_generic_to_shared(smem_dst);
    asm volatile("cp.async.cg.shared.global [%0], [%1], 16;\n" :: "r"(sa), "l"(gsrc) : "memory");
}
__device__ __forceinline__ void cp_async_commit() {
    asm volatile("cp.async.commit_group;\n" ::: "memory");
}
__device__ __forceinline__ void cp_async_wait_all() {
    asm volatile("cp.async.wait_group 0;\n" ::: "memory");
}

// ============================================================
// xproj for z and dv chunks only (r chunk is dead in the reference).
// ============================================================
__global__ void __launch_bounds__(256) k_xproj(const float* __restrict__ x,
                                               const float* __restrict__ x2h_v,
                                               const float* __restrict__ x2h_g,
                                               const float* __restrict__ x2h_b) {
    __shared__ float xs[8 * 512]; // 16 KB
    int n = (blockIdx.x < 2) ? (blockIdx.x * 256 + threadIdx.x)
                             : (1024 + (blockIdx.x - 2) * 256 + threadIdx.x);
    int m0 = blockIdx.y * 8;
    for (int idx = threadIdx.x; idx < 8 * 512; idx += 256)
        xs[idx] = x[(m0 + (idx >> 9)) * 512 + (idx & 511)];
    __syncthreads();
    float acc[8];
#pragma unroll
    for (int m = 0; m < 8; m++) acc[m] = 0.f;
    float ss = 0.f;
    const float4* wrow4 = (const float4*)(x2h_v + n * 512);
#pragma unroll 2
    for (int c = 0; c < 128; c++) {
        float4 w4 = wrow4[c];
        ss = fmaf(w4.x, w4.x, ss); ss = fmaf(w4.y, w4.y, ss);
        ss = fmaf(w4.z, w4.z, ss); ss = fmaf(w4.w, w4.w, ss);
#pragma unroll
        for (int m = 0; m < 8; m++) {
            float4 x4 = ((const float4*)(xs + m * 512))[c];
            acc[m] = fmaf(w4.x, x4.x, acc[m]);
            acc[m] = fmaf(w4.y, x4.y, acc[m]);
            acc[m] = fmaf(w4.z, x4.z, acc[m]);
            acc[m] = fmaf(w4.w, x4.w, acc[m]);
        }
    }
    float sc = x2h_g[n] * rsqrtf(ss);
    float bb = x2h_b[n];
#pragma unroll
    for (int m = 0; m < 8; m++)
        g_xproj[(m0 + m) * H3 + n] = fmaf(acc[m], sc, bb);
}

// ============================================================
// Grid-wide software barrier (NBLK participants).
// ============================================================
__device__ __forceinline__ void grid_bar(unsigned &lgen, int fidx) {
    __syncthreads();
    __threadfence();
    if (threadIdx.x == 0) {
        unsigned a = atomicAdd(&g_count, 1u);
        if (a == NBLK - 1u) {
            g_count = 0u;
            __threadfence();
#pragma unroll
            for (int f = 0; f < 16; f++)
                ((volatile unsigned*)g_flag)[f * 32] = lgen + 1u;
        } else {
            volatile unsigned* vf = &g_flag[fidx * 32];
            while (*vf == lgen) { }
        }
        lgen += 1u;
    }
    __syncthreads();
}

__device__ __forceinline__ float sigf(float x) { return 1.f / (1.f + __expf(-x)); }
__device__ __forceinline__ float sshr(float y) {
    return (y > 0.5f) ? y - 0.5f : ((y < -0.5f) ? y + 0.5f : 0.f);
}

// ============================================================
// Persistent scan: 256 blocks own 2 rows each (iA=blk, iB=blk+256).
// Row A dU/tE in SMEM, row B dU/tE in REGISTERS. hn double-buffered in
// SMEM, staged with cp.async (no registers) overlapped with te update.
// All xproj scalars this block ever needs preloaded into SMEM at init.
// ============================================================
__global__ void __launch_bounds__(256, 2) k_scan(
    const float* __restrict__ h0, const float* __restrict__ v0,
    const float* __restrict__ dU0, const float* __restrict__ te0,
    const float* __restrict__ tE0, const float* __restrict__ alpha,
    const float* __restrict__ h2h_v, const float* __restrict__ h2h_g,
    const float* __restrict__ h2h_b, const float* __restrict__ h2mod_w,
    const float* __restrict__ h2mod_b, const float* __restrict__ modU_w,
    const float* __restrict__ modU_b, float* __restrict__ out)
{
    extern __shared__ float sm[];
    float* s_hn0 = sm;             // 4096 (h buffer 0)
    float* s_hn1 = s_hn0 + 4096;   // 4096 (h buffer 1)
    float* sdU   = s_hn1 + 4096;   // 4096 (row A)
    float* stE   = sdU + 4096;     // 4096 (row A)
    float* s_wzA = stE + 4096;     // 512
    float* s_wdA = s_wzA + 512;    // 512
    float* s_wzB = s_wdA + 512;    // 512
    float* s_wdB = s_wzB + 512;    // 512
    float* s_xp  = s_wdB + 512;    // 1024: [m][{zA,dA,zB,dB}] for m=0..255
    // total 19456 floats = 77824 B

    __shared__ float sv[16], s_dvacc[16];
    __shared__ float s_hniA[8], s_hniB[8], s_teiA[8], s_teiB[8];
    __shared__ float s_g[32];
    __shared__ float s_red[8][16];
    __shared__ float s_sc[6];
    __shared__ float s_mw8[8], s_mb[4];

    const int iA = blockIdx.x, iB = iA + 256;
    const int tid = threadIdx.x;
    const int wb = tid >> 5, lane = tid & 31;
    const int fidx = blockIdx.x & 15;
    unsigned lgen = ((volatile unsigned*)g_flag)[fidx * 32];

    if (tid < 8) s_mw8[tid] = h2mod_w[(tid & 3) * 512 + ((tid < 4) ? iA : iB)];
    if (tid < 4) s_mb[tid] = h2mod_b[tid];
    const float bzA = h2h_b[iA], bdA = h2h_b[2 * Hd + iA];
    const float bzB = h2h_b[iB], bdB = h2h_b[2 * Hd + iB];

    // ---- preload all 1024 xproj scalars this block needs ----
    {
        int m = tid;                      // 256 m-values, 4 scalars each
        const float* xp = g_xproj + m * H3;
        s_xp[m * 4 + 0] = xp[iA];
        s_xp[m * 4 + 1] = xp[2 * Hd + iA];
        s_xp[m * 4 + 2] = xp[iB];
        s_xp[m * 4 + 3] = xp[2 * Hd + iB];
    }

    // ---- inline weight-norm: 6 h2h rows (z/r/d for iA and iB) ----
    float2 vzA = ((const float2*)(h2h_v + iA * Hd))[tid];
    float2 vrA = ((const float2*)(h2h_v + (Hd + iA) * Hd))[tid];
    float2 vdA = ((const float2*)(h2h_v + (2 * Hd + iA) * Hd))[tid];
    float2 vzB = ((const float2*)(h2h_v + iB * Hd))[tid];
    float2 vrB = ((const float2*)(h2h_v + (Hd + iB) * Hd))[tid];
    float2 vdB = ((const float2*)(h2h_v + (2 * Hd + iB) * Hd))[tid];
    {
        float s0 = vzA.x * vzA.x + vzA.y * vzA.y;
        float s1 = vrA.x * vrA.x + vrA.y * vrA.y;
        float s2 = vdA.x * vdA.x + vdA.y * vdA.y;
        float s3 = vzB.x * vzB.x + vzB.y * vzB.y;
        float s4 = vrB.x * vrB.x + vrB.y * vrB.y;
        float s5 = vdB.x * vdB.x + vdB.y * vdB.y;
#pragma unroll
        for (int o = 16; o; o >>= 1) {
            s0 += __shfl_xor_sync(0xffffffffu, s0, o);
            s1 += __shfl_xor_sync(0xffffffffu, s1, o);
            s2 += __shfl_xor_sync(0xffffffffu, s2, o);
            s3 += __shfl_xor_sync(0xffffffffu, s3, o);
            s4 += __shfl_xor_sync(0xffffffffu, s4, o);
            s5 += __shfl_xor_sync(0xffffffffu, s5, o);
        }
        if (lane == 0) {
            s_red[wb][0] = s0; s_red[wb][1] = s1; s_red[wb][2] = s2;
            s_red[wb][3] = s3; s_red[wb][4] = s4; s_red[wb][5] = s5;
        }
    }
    __syncthreads();
    if (tid < 6) {
        float s = 0.f;
#pragma unroll
        for (int w2 = 0; w2 < 8; w2++) s += s_red[w2][tid];
        int col = (tid < 3) ? iA : iB;
        int row = (tid % 3) * Hd + col;
        s_sc[tid] = h2h_g[row] * rsqrtf(s);
    }
    __syncthreads();

    // per-row constants into registers (+ wz/wd into smem)
    float2 alA, alB, wvA, wvB, bvA, bvB, loA, loB, upA, upB;
    {
        ((float2*)s_wzA)[tid] = make_float2(vzA.x * s_sc[0], vzA.y * s_sc[0]);
        ((float2*)s_wdA)[tid] = make_float2(vdA.x * s_sc[2], vdA.y * s_sc[2]);
        ((float2*)s_wzB)[tid] = make_float2(vzB.x * s_sc[3], vzB.y * s_sc[3]);
        ((float2*)s_wdB)[tid] = make_float2(vdB.x * s_sc[5], vdB.y * s_sc[5]);
        alA = ((const float2*)(alpha + iA * Hd))[tid];
        alB = ((const float2*)(alpha + iB * Hd))[tid];
        wvA = ((const float2*)(modU_w + iA * Hd))[tid];
        wvB = ((const float2*)(modU_w + iB * Hd))[tid];
        bvA = ((const float2*)(modU_b + iA * Hd))[tid];
        bvB = ((const float2*)(modU_b + iB * Hd))[tid];
        float wrx = vrA.x * s_sc[1], wry = vrA.y * s_sc[1];
        float ax = alA.x + 1e-5f, ay = alA.y + 1e-5f;
        upA = make_float2(fmaxf(1.f - wrx, 0.f) / ax, fmaxf(1.f - wry, 0.f) / ay);
        loA = make_float2(-fmaxf(1.f + wrx, 0.f) / ax, -fmaxf(1.f + wry, 0.f) / ay);
        wrx = vrB.x * s_sc[4]; wry = vrB.y * s_sc[4];
        ax = alB.x + 1e-5f; ay = alB.y + 1e-5f;
        upB = make_float2(fmaxf(1.f - wrx, 0.f) / ax, fmaxf(1.f - wry, 0.f) / ay);
        loB = make_float2(-fmaxf(1.f + wrx, 0.f) / ax, -fmaxf(1.f + wry, 0.f) / ay);
    }

    // ---- stage h0 and init state ----
    for (int idx = tid; idx < 1024; idx += 256)
        ((float4*)s_hn0)[idx] = ((const float4*)h0)[idx];

    float2 te[8], dUB[8], tEB[8];
#pragma unroll
    for (int u = 0; u < 8; u++) {
        float2 dA = ((const float2*)(dU0 + (u * Hd + iA) * Hd))[tid];
        ((float2*)sdU)[u * 256 + tid] = dA;
        ((float2*)stE)[u * 256 + tid] = ((const float2*)(tE0 + (u * Hd + iA) * Hd))[tid];
        dUB[u] = ((const float2*)(dU0 + (u * Hd + iB) * Hd))[tid];
        tEB[u] = ((const float2*)(tE0 + (u * Hd + iB) * Hd))[tid];
        te[u] = ((const float2*)(te0 + u * Hd))[tid];
        float2 h2 = ((const float2*)(h0 + u * Hd))[tid];
        float accA = alA.x * dA.x * h2.x + alA.y * dA.y * h2.y;
        float accB = alB.x * dUB[u].x * h2.x + alB.y * dUB[u].y * h2.y;
#pragma unroll
        for (int o = 16; o; o >>= 1) {
            accA += __shfl_xor_sync(0xffffffffu, accA, o);
            accB += __shfl_xor_sync(0xffffffffu, accB, o);
        }
        if (lane == 0) { s_red[wb][u] = accA; s_red[wb][8 + u] = accB; }
    }
    if (tid < 16) sv[tid] = v0[(tid & 7) * Hd + ((tid < 8) ? iA : iB)];
    __syncthreads();
    if (tid < 16) {
        float s = 0.f;
#pragma unroll
        for (int w2 = 0; w2 < 8; w2++) s += s_red[w2][tid];
        s_dvacc[tid] = s;
    }
    __syncthreads();

    for (int t = 0; t < Td; t++) {
        float* hn_buf = g_hbuf[t & 1];
        float* s_cur = (t & 1) ? s_hn1 : s_hn0;   // holds h_t
        float* s_nxt = (t & 1) ? s_hn0 : s_hn1;   // will hold h_{t+1}

        // ---- phase A: hn for rows iA,iB, batch wb (warp = batch) ----
        {
            float xpzA = 0.f, xpdA = 0.f, xpzB = 0.f, xpdB = 0.f;
            float dvA = 0.f, dvB = 0.f, voA = 0.f, voB = 0.f;
            if (lane == 0) {
                const float* xp = s_xp + (t * Bd + wb) * 4;   // smem, no L2 latency
                xpzA = xp[0]; xpdA = xp[1]; xpzB = xp[2]; xpdB = xp[3];
                dvA = s_dvacc[wb]; dvB = s_dvacc[8 + wb];
                voA = sv[wb]; voB = sv[8 + wb];
            }
            const float4* hb4 = (const float4*)(s_cur + wb * Hd);
            float azA = 0.f, adA = 0.f, azB = 0.f, adB = 0.f;
#pragma unroll
            for (int it = 0; it < 4; it++) {
                float4 h4 = hb4[lane + 32 * it];
                float4 a4 = ((const float4*)s_wzA)[lane + 32 * it];
                float4 c4 = ((const float4*)s_wdA)[lane + 32 * it];
                float4 e4 = ((const float4*)s_wzB)[lane + 32 * it];
                float4 f4 = ((const float4*)s_wdB)[lane + 32 * it];
                azA = fmaf(a4.x, h4.x, azA); azA = fmaf(a4.y, h4.y, azA);
                azA = fmaf(a4.z, h4.z, azA); azA = fmaf(a4.w, h4.w, azA);
                adA = fmaf(c4.x, h4.x, adA); adA = fmaf(c4.y, h4.y, adA);
                adA = fmaf(c4.z, h4.z, adA); adA = fmaf(c4.w, h4.w, adA);
                azB = fmaf(e4.x, h4.x, azB); azB = fmaf(e4.y, h4.y, azB);
                azB = fmaf(e4.z, h4.z, azB); azB = fmaf(e4.w, h4.w, azB);
                adB = fmaf(f4.x, h4.x, adB); adB = fmaf(f4.y, h4.y, adB);
                adB = fmaf(f4.z, h4.z, adB); adB = fmaf(f4.w, h4.w, adB);
            }
#pragma unroll
            for (int o = 16; o; o >>= 1) {
                azA += __shfl_xor_sync(0xffffffffu, azA, o);
                adA += __shfl_xor_sync(0xffffffffu, adA, o);
                azB += __shfl_xor_sync(0xffffffffu, azB, o);
                adB += __shfl_xor_sync(0xffffffffu, adB, o);
            }
            if (lane == 0) {
                float z  = sigf(xpzA + azA + bzA);
                float dv = xpdA + adA + bdA + dvA;
                float vn = voA + z * (dv - voA);
                sv[wb] = vn;
                float hn = fmaxf(vn, 0.f);
                s_hniA[wb] = hn;
                hn_buf[wb * Hd + iA] = hn;
                out[OFF_OUTS + (t * Bd + wb) * Hd + iA] = hn;
                z  = sigf(xpzB + azB + bzB);
                dv = xpdB + adB + bdB + dvB;
                vn = voB + z * (dv - voB);
                sv[8 + wb] = vn;
                hn = fmaxf(vn, 0.f);
                s_hniB[wb] = hn;
                hn_buf[wb * Hd + iB] = hn;
                out[OFF_OUTS + (t * Bd + wb) * Hd + iB] = hn;
            }
        }
        __syncthreads();
        // combined gate contribution for both rows: one atomic per gate slot
        if (tid < 32) {
            int bb = tid >> 2, g = tid & 3;
            float v = s_mw8[g] * s_hniA[bb] + s_mw8[4 + g] * s_hniB[bb];
            atomicAdd(&g_gates[t & 3][tid], v);
        }

        grid_bar(lgen, fidx);

        // ---- stage NEW hn into s_nxt via cp.async (no registers) ----
#pragma unroll
        for (int k = 0; k < 4; k++)
            cp_async16(s_nxt + 4 * (tid + 256 * k), hn_buf + 4 * (tid + 256 * k));
        cp_async_commit();

        // ---- gates: read finished sums, apply activations ----
        if (tid < 32) {
            float v = __ldcg(&g_gates[t & 3][tid]) + s_mb[tid & 3];
            s_g[tid] = ((tid & 3) == 3) ? fmaxf(v, 0.f) : sigf(v);
        }
        if (iA == 0 && tid >= 64 && tid < 96)
            g_gates[(t + 2) & 3][tid - 64] = 0.f;
        __syncthreads();   // s_g ready

        // ---- te update (uses OLD h still in s_cur; cp.async in flight) ----
#pragma unroll
        for (int u = 0; u < 8; u++) {
            float taue = s_g[u * 4 + 0];
            float2 h2 = ((const float2*)s_cur)[u * 256 + tid];
            te[u].x += taue * (h2.x - te[u].x);
            te[u].y += taue * (h2.y - te[u].y);
        }
        if (tid == (iA >> 1)) {
#pragma unroll
            for (int u = 0; u < 8; u++)
                s_teiA[u] = (iA & 1) ? te[u].y : te[u].x;
        }
        if (tid == (iB >> 1)) {
#pragma unroll
            for (int u = 0; u < 8; u++)
                s_teiB[u] = (iB & 1) ? te[u].y : te[u].x;
        }
        cp_async_wait_all();
        __syncthreads();   // s_nxt + s_tei ready

        // ---- main state update (rows A smem, B regs) + fused matvec ----
#pragma unroll
        for (int u = 0; u < 8; u++) {
            float2 hnj = ((const float2*)s_nxt)[u * 256 + tid];
            float tauE = s_g[u * 4 + 1], tauU = s_g[u * 4 + 2], mU = s_g[u * 4 + 3];
            float2 tn = te[u];
            // row A
            float hni = s_hniA[u], tei = s_teiA[u];
            float ox = hni * tn.x - tei * hnj.x;
            float oy = hni * tn.y - tei * hnj.y;
            float2 E = ((float2*)stE)[u * 256 + tid];
            E.x += tauE * (ox - E.x);
            E.y += tauE * (oy - E.y);
            ((float2*)stE)[u * 256 + tid] = E;
            float2 D = ((float2*)sdU)[u * 256 + tid];
            D.x += tauU * (sshr(fmaf(mU, wvA.x, bvA.x)) * E.x - D.x);
            D.y += tauU * (sshr(fmaf(mU, wvA.y, bvA.y)) * E.y - D.y);
            D.x = fminf(fmaxf(D.x, loA.x), upA.x);
            D.y = fminf(fmaxf(D.y, loA.y), upA.y);
            ((float2*)sdU)[u * 256 + tid] = D;
            float accA = alA.x * D.x * hnj.x + alA.y * D.y * hnj.y;
            // row B (registers)
            hni = s_hniB[u]; tei = s_teiB[u];
            ox = hni * tn.x - tei * hnj.x;
            oy = hni * tn.y - tei * hnj.y;
            tEB[u].x += tauE * (ox - tEB[u].x);
            tEB[u].y += tauE * (oy - tEB[u].y);
            dUB[u].x += tauU * (sshr(fmaf(mU, wvB.x, bvB.x)) * tEB[u].x - dUB[u].x);
            dUB[u].y += tauU * (sshr(fmaf(mU, wvB.y, bvB.y)) * tEB[u].y - dUB[u].y);
            dUB[u].x = fminf(fmaxf(dUB[u].x, loB.x), upB.x);
            dUB[u].y = fminf(fmaxf(dUB[u].y, loB.y), upB.y);
            float accB = alB.x * dUB[u].x * hnj.x + alB.y * dUB[u].y * hnj.y;
#pragma unroll
            for (int o = 16; o; o >>= 1) {
                accA += __shfl_xor_sync(0xffffffffu, accA, o);
                accB += __shfl_xor_sync(0xffffffffu, accB, o);
            }
            if (lane == 0) { s_red[wb][u] = accA; s_red[wb][8 + u] = accB; }
        }
        __syncthreads();
        if (tid < 16) {
            float s = 0.f;
#pragma unroll
            for (int w2 = 0; w2 < 8; w2++) s += s_red[w2][tid];
            s_dvacc[tid] = s;
        }
        __syncthreads();
    }

    // ---- epilogue: dump final state ----
    if (tid < 16) {
        int b = tid & 7, col = (tid < 8) ? iA : iB;
        out[OFF_V + b * Hd + col] = sv[tid];
        out[OFF_H + b * Hd + col] = (tid < 8) ? s_hniA[b] : s_hniB[b];
    }
#pragma unroll
    for (int u = 0; u < 8; u++) {
        ((float2*)(out + OFF_DU  + (u * Hd + iA) * Hd))[tid] = ((float2*)sdU)[u * 256 + tid];
        ((float2*)(out + OFF_TEE + (u * Hd + iA) * Hd))[tid] = ((float2*)stE)[u * 256 + tid];
        ((float2*)(out + OFF_DU  + (u * Hd + iB) * Hd))[tid] = dUB[u];
        ((float2*)(out + OFF_TEE + (u * Hd + iB) * Hd))[tid] = tEB[u];
    }
    if (iA == 0) {
#pragma unroll
        for (int u = 0; u < 8; u++)
            ((float2*)(out + OFF_TE + u * Hd))[tid] = te[u];
    }
}

extern "C" void kernel_launch(void* const* d_in, const int* in_sizes, int n_in,
                              void* d_out, int out_size) {
    const float* x       = (const float*)d_in[0];
    const float* h0      = (const float*)d_in[1];
    const float* v0      = (const float*)d_in[2];
    const float* dU0     = (const float*)d_in[3];
    const float* te0     = (const float*)d_in[4];
    const float* tE0     = (const float*)d_in[5];
    const float* x2h_v   = (const float*)d_in[6];
    const float* x2h_g   = (const float*)d_in[7];
    const float* x2h_b   = (const float*)d_in[8];
    const float* h2h_v   = (const float*)d_in[9];
    const float* h2h_g   = (const float*)d_in[10];
    const float* h2h_b   = (const float*)d_in[11];
    const float* alpha   = (const float*)d_in[12];
    const float* h2mod_w = (const float*)d_in[13];
    const float* h2mod_b = (const float*)d_in[14];
    const float* modU_w  = (const float*)d_in[15];
    const float* modU_b  = (const float*)d_in[16];
    float* out = (float*)d_out;

    const int scan_smem = 19456 * sizeof(float); // 77824 B
    cudaFuncSetAttribute(k_scan, cudaFuncAttributeMaxDynamicSharedMemorySize, scan_smem);

    k_xproj<<<dim3(4, 32), 256>>>(x, x2h_v, x2h_g, x2h_b);
    k_scan<<<NBLK, 256, scan_smem>>>(h0, v0, dU0, te0, tE0, alpha,
                                     h2h_v, h2h_g, h2h_b,
                                     h2mod_w, h2mod_b, modU_w, modU_b, out);
}

// round 13
// speedup vs baseline: 1.4555x; 1.1304x over previous
#include <cuda_runtime.h>
#include <math.h>

#define Td 32
#define Bd 8
#define Id 512
#define Hd 512
#define H3 1536
#define NBLK 256

// ---- output layout (concatenated tuple: v, h, dU, te, tE, outs) ----
#define OFF_V    0
#define OFF_H    4096
#define OFF_DU   8192
#define OFF_TE   2105344
#define OFF_TEE  2109440
#define OFF_OUTS 4206592

// ---- scratch (device globals; no allocation allowed) ----
__device__ float g_xproj[Td * Bd * H3]; // 1.5 MB (middle third unused)
__device__ float g_hbuf[2][Bd * Hd];    // ping-pong hidden state
__device__ unsigned g_count = 0;
__device__ unsigned g_flag[16 * 32];    // 16 broadcast flags, 128B apart
__device__ float g_gates[4][32];        // rotating gate accumulators [t&3][b*4+g]

// ============================================================
// xproj for z and dv chunks only (r chunk is dead in the reference).
// ============================================================
__global__ void __launch_bounds__(256) k_xproj(const float* __restrict__ x,
                                               const float* __restrict__ x2h_v,
                                               const float* __restrict__ x2h_g,
                                               const float* __restrict__ x2h_b) {
    __shared__ float xs[8 * 512]; // 16 KB
    int n = (blockIdx.x < 2) ? (blockIdx.x * 256 + threadIdx.x)
                             : (1024 + (blockIdx.x - 2) * 256 + threadIdx.x);
    int m0 = blockIdx.y * 8;
    for (int idx = threadIdx.x; idx < 8 * 512; idx += 256)
        xs[idx] = x[(m0 + (idx >> 9)) * 512 + (idx & 511)];
    __syncthreads();
    float acc[8];
#pragma unroll
    for (int m = 0; m < 8; m++) acc[m] = 0.f;
    float ss = 0.f;
    const float4* wrow4 = (const float4*)(x2h_v + n * 512);
#pragma unroll 2
    for (int c = 0; c < 128; c++) {
        float4 w4 = wrow4[c];
        ss = fmaf(w4.x, w4.x, ss); ss = fmaf(w4.y, w4.y, ss);
        ss = fmaf(w4.z, w4.z, ss); ss = fmaf(w4.w, w4.w, ss);
#pragma unroll
        for (int m = 0; m < 8; m++) {
            float4 x4 = ((const float4*)(xs + m * 512))[c];
            acc[m] = fmaf(w4.x, x4.x, acc[m]);
            acc[m] = fmaf(w4.y, x4.y, acc[m]);
            acc[m] = fmaf(w4.z, x4.z, acc[m]);
            acc[m] = fmaf(w4.w, x4.w, acc[m]);
        }
    }
    float sc = x2h_g[n] * rsqrtf(ss);
    float bb = x2h_b[n];
#pragma unroll
    for (int m = 0; m < 8; m++)
        g_xproj[(m0 + m) * H3 + n] = fmaf(acc[m], sc, bb);
}

// ============================================================
// Grid-wide software barrier (NBLK participants).
// ============================================================
__device__ __forceinline__ void grid_bar(unsigned &lgen, int fidx) {
    __syncthreads();
    __threadfence();
    if (threadIdx.x == 0) {
        unsigned a = atomicAdd(&g_count, 1u);
        if (a == NBLK - 1u) {
            g_count = 0u;
            __threadfence();
#pragma unroll
            for (int f = 0; f < 16; f++)
                ((volatile unsigned*)g_flag)[f * 32] = lgen + 1u;
        } else {
            volatile unsigned* vf = &g_flag[fidx * 32];
            while (*vf == lgen) { }
        }
        lgen += 1u;
    }
    __syncthreads();
}

__device__ __forceinline__ float sigf(float x) { return 1.f / (1.f + __expf(-x)); }
__device__ __forceinline__ float sshr(float y) {
    return (y > 0.5f) ? y - 0.5f : ((y < -0.5f) ? y + 0.5f : 0.f);
}

// ============================================================
// Persistent scan: 256 blocks own 2 rows each (iA=blk, iB=blk+256).
// NO smem h buffer: each thread carries h[b, j-pair] in registers (hj).
// Phase A = block-wide reduction of register partials (weights in regs).
// Row A dU/tE in SMEM, row B dU/tE in REGISTERS.
// ============================================================
__global__ void __launch_bounds__(256, 2) k_scan(
    const float* __restrict__ h0, const float* __restrict__ v0,
    const float* __restrict__ dU0, const float* __restrict__ te0,
    const float* __restrict__ tE0, const float* __restrict__ alpha,
    const float* __restrict__ h2h_v, const float* __restrict__ h2h_g,
    const float* __restrict__ h2h_b, const float* __restrict__ h2mod_w,
    const float* __restrict__ h2mod_b, const float* __restrict__ modU_w,
    const float* __restrict__ modU_b, float* __restrict__ out)
{
    extern __shared__ float sm[];
    float* sdU   = sm;             // 4096 (row A dU)
    float* stE   = sdU + 4096;     // 4096 (row A tE)
    float* s_xp  = stE + 4096;     // 1024: [m][{zA,dA,zB,dB}]
    float* s_wvA = s_xp + 1024;    // 512
    float* s_bvA = s_wvA + 512;    // 512
    float* s_wvB = s_bvA + 512;    // 512
    float* s_bvB = s_wvB + 512;    // 512
    // total 11264 floats = 45056 B

    __shared__ float sv[16], s_dvacc[16];
    __shared__ float s_hniA[8], s_hniB[8], s_teiA[8], s_teiB[8];
    __shared__ float s_g[32];
    __shared__ float s_redA[8][16], s_redB[8][16];
    __shared__ float s_sc[6];
    __shared__ float s_mw8[8], s_mb[4];

    const int iA = blockIdx.x, iB = iA + 256;
    const int tid = threadIdx.x;
    const int wb = tid >> 5, lane = tid & 31;
    const int fidx = blockIdx.x & 15;
    unsigned lgen = ((volatile unsigned*)g_flag)[fidx * 32];

    if (tid < 8) s_mw8[tid] = h2mod_w[(tid & 3) * 512 + ((tid < 4) ? iA : iB)];
    if (tid < 4) s_mb[tid] = h2mod_b[tid];
    const float bzA = h2h_b[iA], bdA = h2h_b[2 * Hd + iA];
    const float bzB = h2h_b[iB], bdB = h2h_b[2 * Hd + iB];

    // ---- preload all 1024 xproj scalars this block needs ----
    {
        const float* xp = g_xproj + tid * H3;
        s_xp[tid * 4 + 0] = xp[iA];
        s_xp[tid * 4 + 1] = xp[2 * Hd + iA];
        s_xp[tid * 4 + 2] = xp[iB];
        s_xp[tid * 4 + 3] = xp[2 * Hd + iB];
    }

    // ---- inline weight-norm: 6 h2h rows (z/r/d for iA and iB) ----
    float2 vzA = ((const float2*)(h2h_v + iA * Hd))[tid];
    float2 vrA = ((const float2*)(h2h_v + (Hd + iA) * Hd))[tid];
    float2 vdA = ((const float2*)(h2h_v + (2 * Hd + iA) * Hd))[tid];
    float2 vzB = ((const float2*)(h2h_v + iB * Hd))[tid];
    float2 vrB = ((const float2*)(h2h_v + (Hd + iB) * Hd))[tid];
    float2 vdB = ((const float2*)(h2h_v + (2 * Hd + iB) * Hd))[tid];
    {
        float s0 = vzA.x * vzA.x + vzA.y * vzA.y;
        float s1 = vrA.x * vrA.x + vrA.y * vrA.y;
        float s2 = vdA.x * vdA.x + vdA.y * vdA.y;
        float s3 = vzB.x * vzB.x + vzB.y * vzB.y;
        float s4 = vrB.x * vrB.x + vrB.y * vrB.y;
        float s5 = vdB.x * vdB.x + vdB.y * vdB.y;
#pragma unroll
        for (int o = 16; o; o >>= 1) {
            s0 += __shfl_xor_sync(0xffffffffu, s0, o);
            s1 += __shfl_xor_sync(0xffffffffu, s1, o);
            s2 += __shfl_xor_sync(0xffffffffu, s2, o);
            s3 += __shfl_xor_sync(0xffffffffu, s3, o);
            s4 += __shfl_xor_sync(0xffffffffu, s4, o);
            s5 += __shfl_xor_sync(0xffffffffu, s5, o);
        }
        if (lane == 0) {
            s_redA[wb][0] = s0; s_redA[wb][1] = s1; s_redA[wb][2] = s2;
            s_redA[wb][3] = s3; s_redA[wb][4] = s4; s_redA[wb][5] = s5;
        }
    }
    __syncthreads();
    if (tid < 6) {
        float s = 0.f;
#pragma unroll
        for (int w2 = 0; w2 < 8; w2++) s += s_redA[w2][tid];
        int col = (tid < 3) ? iA : iB;
        int row = (tid % 3) * Hd + col;
        s_sc[tid] = h2h_g[row] * rsqrtf(s);
    }
    __syncthreads();

    // recurrent weights for this thread's j-pair -> REGISTERS
    float2 wzA2 = make_float2(vzA.x * s_sc[0], vzA.y * s_sc[0]);
    float2 wdA2 = make_float2(vdA.x * s_sc[2], vdA.y * s_sc[2]);
    float2 wzB2 = make_float2(vzB.x * s_sc[3], vzB.y * s_sc[3]);
    float2 wdB2 = make_float2(vdB.x * s_sc[5], vdB.y * s_sc[5]);

    // per-row constants
    float2 alA, alB, loA, loB, upA, upB;
    {
        alA = ((const float2*)(alpha + iA * Hd))[tid];
        alB = ((const float2*)(alpha + iB * Hd))[tid];
        ((float2*)s_wvA)[tid] = ((const float2*)(modU_w + iA * Hd))[tid];
        ((float2*)s_wvB)[tid] = ((const float2*)(modU_w + iB * Hd))[tid];
        ((float2*)s_bvA)[tid] = ((const float2*)(modU_b + iA * Hd))[tid];
        ((float2*)s_bvB)[tid] = ((const float2*)(modU_b + iB * Hd))[tid];
        float wrx = vrA.x * s_sc[1], wry = vrA.y * s_sc[1];
        float ax = alA.x + 1e-5f, ay = alA.y + 1e-5f;
        upA = make_float2(fmaxf(1.f - wrx, 0.f) / ax, fmaxf(1.f - wry, 0.f) / ay);
        loA = make_float2(-fmaxf(1.f + wrx, 0.f) / ax, -fmaxf(1.f + wry, 0.f) / ay);
        wrx = vrB.x * s_sc[4]; wry = vrB.y * s_sc[4];
        ax = alB.x + 1e-5f; ay = alB.y + 1e-5f;
        upB = make_float2(fmaxf(1.f - wrx, 0.f) / ax, fmaxf(1.f - wry, 0.f) / ay);
        loB = make_float2(-fmaxf(1.f + wrx, 0.f) / ax, -fmaxf(1.f + wry, 0.f) / ay);
    }

    // ---- init state: hj (h regs), te, dU/tE, dvacc ----
    float2 te[8], hj[8], dUB[8], tEB[8];
#pragma unroll
    for (int u = 0; u < 8; u++) {
        float2 dA = ((const float2*)(dU0 + (u * Hd + iA) * Hd))[tid];
        ((float2*)sdU)[u * 256 + tid] = dA;
        ((float2*)stE)[u * 256 + tid] = ((const float2*)(tE0 + (u * Hd + iA) * Hd))[tid];
        dUB[u] = ((const float2*)(dU0 + (u * Hd + iB) * Hd))[tid];
        tEB[u] = ((const float2*)(tE0 + (u * Hd + iB) * Hd))[tid];
        te[u] = ((const float2*)(te0 + u * Hd))[tid];
        hj[u] = ((const float2*)(h0 + u * Hd))[tid];
        float accA = alA.x * dA.x * hj[u].x + alA.y * dA.y * hj[u].y;
        float accB = alB.x * dUB[u].x * hj[u].x + alB.y * dUB[u].y * hj[u].y;
#pragma unroll
        for (int o = 16; o; o >>= 1) {
            accA += __shfl_xor_sync(0xffffffffu, accA, o);
            accB += __shfl_xor_sync(0xffffffffu, accB, o);
        }
        if (lane == 0) { s_redA[wb][u] = accA; s_redA[wb][8 + u] = accB; }
    }
    if (tid < 16) sv[tid] = v0[(tid & 7) * Hd + ((tid < 8) ? iA : iB)];
    __syncthreads();
    if (tid < 16) {
        float s = 0.f;
#pragma unroll
        for (int w2 = 0; w2 < 8; w2++) s += s_redA[w2][tid];
        s_dvacc[tid] = s;
    }
    __syncthreads();

    for (int t = 0; t < Td; t++) {
        float* hn_buf = g_hbuf[t & 1];

        // ---- phase A: block-reduced dots from register weights + hj ----
        {
            float pz[8], pd[8];
#pragma unroll
            for (int u = 0; u < 8; u++) {
                pz[u] = wzA2.x * hj[u].x + wzA2.y * hj[u].y;
                pd[u] = wdA2.x * hj[u].x + wdA2.y * hj[u].y;
            }
#pragma unroll
            for (int o = 16; o; o >>= 1) {
#pragma unroll
                for (int u = 0; u < 8; u++) {
                    pz[u] += __shfl_xor_sync(0xffffffffu, pz[u], o);
                    pd[u] += __shfl_xor_sync(0xffffffffu, pd[u], o);
                }
            }
            if (lane == 0) {
#pragma unroll
                for (int u = 0; u < 8; u++) {
                    s_redA[wb][u] = pz[u]; s_redA[wb][8 + u] = pd[u];
                }
            }
            // pass B (reuse regs)
#pragma unroll
            for (int u = 0; u < 8; u++) {
                pz[u] = wzB2.x * hj[u].x + wzB2.y * hj[u].y;
                pd[u] = wdB2.x * hj[u].x + wdB2.y * hj[u].y;
            }
#pragma unroll
            for (int o = 16; o; o >>= 1) {
#pragma unroll
                for (int u = 0; u < 8; u++) {
                    pz[u] += __shfl_xor_sync(0xffffffffu, pz[u], o);
                    pd[u] += __shfl_xor_sync(0xffffffffu, pd[u], o);
                }
            }
            if (lane == 0) {
#pragma unroll
                for (int u = 0; u < 8; u++) {
                    s_redB[wb][u] = pz[u]; s_redB[wb][8 + u] = pd[u];
                }
            }
        }
        __syncthreads();
        if (tid < 8) {
            int b = tid;
            float az = 0.f, ad = 0.f;
#pragma unroll
            for (int w2 = 0; w2 < 8; w2++) { az += s_redA[w2][b]; ad += s_redA[w2][8 + b]; }
            const float* xp = s_xp + (t * Bd + b) * 4;
            float z  = sigf(xp[0] + az + bzA);
            float dv = xp[1] + ad + bdA + s_dvacc[b];
            float vo = sv[b];
            float vn = vo + z * (dv - vo);
            sv[b] = vn;
            float hn = fmaxf(vn, 0.f);
            s_hniA[b] = hn;
            hn_buf[b * Hd + iA] = hn;
            out[OFF_OUTS + (t * Bd + b) * Hd + iA] = hn;
        } else if (tid < 16) {
            int b = tid - 8;
            float az = 0.f, ad = 0.f;
#pragma unroll
            for (int w2 = 0; w2 < 8; w2++) { az += s_redB[w2][b]; ad += s_redB[w2][8 + b]; }
            const float* xp = s_xp + (t * Bd + b) * 4;
            float z  = sigf(xp[2] + az + bzB);
            float dv = xp[3] + ad + bdB + s_dvacc[8 + b];
            float vo = sv[8 + b];
            float vn = vo + z * (dv - vo);
            sv[8 + b] = vn;
            float hn = fmaxf(vn, 0.f);
            s_hniB[b] = hn;
            hn_buf[b * Hd + iB] = hn;
            out[OFF_OUTS + (t * Bd + b) * Hd + iB] = hn;
        }
        __syncthreads();
        // combined gate contribution (one atomic per gate slot per block)
        if (tid < 32) {
            int bb = tid >> 2, g = tid & 3;
            float v = s_mw8[g] * s_hniA[bb] + s_mw8[4 + g] * s_hniB[bb];
            atomicAdd(&g_gates[t & 3][tid], v);
        }

        grid_bar(lgen, fidx);

        // ---- prefetch new hn for this thread's j-pair (overlaps gates) ----
        float2 hn_new[8];
#pragma unroll
        for (int u = 0; u < 8; u++)
            hn_new[u] = __ldcg((const float2*)(hn_buf + u * Hd) + tid);

        // ---- gates: read finished sums, apply activations ----
        if (tid < 32) {
            float v = __ldcg(&g_gates[t & 3][tid]) + s_mb[tid & 3];
            s_g[tid] = ((tid & 3) == 3) ? fmaxf(v, 0.f) : sigf(v);
        }
        if (iA == 0 && tid >= 64 && tid < 96)
            g_gates[(t + 2) & 3][tid - 64] = 0.f;
        __syncthreads();   // s_g ready

        // ---- te update with OLD hj; then hj <- new hn ----
#pragma unroll
        for (int u = 0; u < 8; u++) {
            float taue = s_g[u * 4 + 0];
            te[u].x += taue * (hj[u].x - te[u].x);
            te[u].y += taue * (hj[u].y - te[u].y);
        }
        if (tid == (iA >> 1)) {
#pragma unroll
            for (int u = 0; u < 8; u++)
                s_teiA[u] = (iA & 1) ? te[u].y : te[u].x;
        }
        if (tid == (iB >> 1)) {
#pragma unroll
            for (int u = 0; u < 8; u++)
                s_teiB[u] = (iB & 1) ? te[u].y : te[u].x;
        }
#pragma unroll
        for (int u = 0; u < 8; u++) hj[u] = hn_new[u];
        __syncthreads();   // s_tei ready

        // ---- main state update (rows A smem, B regs) + fused matvec ----
        {
            float2 wA = ((const float2*)s_wvA)[tid];
            float2 bA = ((const float2*)s_bvA)[tid];
            float2 wB = ((const float2*)s_wvB)[tid];
            float2 bB = ((const float2*)s_bvB)[tid];
#pragma unroll
            for (int u = 0; u < 8; u++) {
                float2 hnj = hj[u];
                float tauE = s_g[u * 4 + 1], tauU = s_g[u * 4 + 2], mU = s_g[u * 4 + 3];
                float2 tn = te[u];
                // row A
                float hni = s_hniA[u], tei = s_teiA[u];
                float ox = hni * tn.x - tei * hnj.x;
                float oy = hni * tn.y - tei * hnj.y;
                float2 E = ((float2*)stE)[u * 256 + tid];
                E.x += tauE * (ox - E.x);
                E.y += tauE * (oy - E.y);
                ((float2*)stE)[u * 256 + tid] = E;
                float2 D = ((float2*)sdU)[u * 256 + tid];
                D.x += tauU * (sshr(fmaf(mU, wA.x, bA.x)) * E.x - D.x);
                D.y += tauU * (sshr(fmaf(mU, wA.y, bA.y)) * E.y - D.y);
                D.x = fminf(fmaxf(D.x, loA.x), upA.x);
                D.y = fminf(fmaxf(D.y, loA.y), upA.y);
                ((float2*)sdU)[u * 256 + tid] = D;
                float accA = alA.x * D.x * hnj.x + alA.y * D.y * hnj.y;
                // row B (registers)
                hni = s_hniB[u]; tei = s_teiB[u];
                ox = hni * tn.x - tei * hnj.x;
                oy = hni * tn.y - tei * hnj.y;
                tEB[u].x += tauE * (ox - tEB[u].x);
                tEB[u].y += tauE * (oy - tEB[u].y);
                dUB[u].x += tauU * (sshr(fmaf(mU, wB.x, bB.x)) * tEB[u].x - dUB[u].x);
                dUB[u].y += tauU * (sshr(fmaf(mU, wB.y, bB.y)) * tEB[u].y - dUB[u].y);
                dUB[u].x = fminf(fmaxf(dUB[u].x, loB.x), upB.x);
                dUB[u].y = fminf(fmaxf(dUB[u].y, loB.y), upB.y);
                float accB = alB.x * dUB[u].x * hnj.x + alB.y * dUB[u].y * hnj.y;
#pragma unroll
                for (int o = 16; o; o >>= 1) {
                    accA += __shfl_xor_sync(0xffffffffu, accA, o);
                    accB += __shfl_xor_sync(0xffffffffu, accB, o);
                }
                if (lane == 0) { s_redA[wb][u] = accA; s_redA[wb][8 + u] = accB; }
            }
        }
        __syncthreads();
        if (tid < 16) {
            float s = 0.f;
#pragma unroll
            for (int w2 = 0; w2 < 8; w2++) s += s_redA[w2][tid];
            s_dvacc[tid] = s;
        }
        __syncthreads();
    }

    // ---- epilogue: dump final state ----
    if (tid < 16) {
        int b = tid & 7, col = (tid < 8) ? iA : iB;
        out[OFF_V + b * Hd + col] = sv[tid];
        out[OFF_H + b * Hd + col] = (tid < 8) ? s_hniA[b] : s_hniB[b];
    }
#pragma unroll
    for (int u = 0; u < 8; u++) {
        ((float2*)(out + OFF_DU  + (u * Hd + iA) * Hd))[tid] = ((float2*)sdU)[u * 256 + tid];
        ((float2*)(out + OFF_TEE + (u * Hd + iA) * Hd))[tid] = ((float2*)stE)[u * 256 + tid];
        ((float2*)(out + OFF_DU  + (u * Hd + iB) * Hd))[tid] = dUB[u];
        ((float2*)(out + OFF_TEE + (u * Hd + iB) * Hd))[tid] = tEB[u];
    }
    if (iA == 0) {
#pragma unroll
        for (int u = 0; u < 8; u++)
            ((float2*)(out + OFF_TE + u * Hd))[tid] = te[u];
    }
}

extern "C" void kernel_launch(void* const* d_in, const int* in_sizes, int n_in,
                              void* d_out, int out_size) {
    const float* x       = (const float*)d_in[0];
    const float* h0      = (const float*)d_in[1];
    const float* v0      = (const float*)d_in[2];
    const float* dU0     = (const float*)d_in[3];
    const float* te0     = (const float*)d_in[4];
    const float* tE0     = (const float*)d_in[5];
    const float* x2h_v   = (const float*)d_in[6];
    const float* x2h_g   = (const float*)d_in[7];
    const float* x2h_b   = (const float*)d_in[8];
    const float* h2h_v   = (const float*)d_in[9];
    const float* h2h_g   = (const float*)d_in[10];
    const float* h2h_b   = (const float*)d_in[11];
    const float* alpha   = (const float*)d_in[12];
    const float* h2mod_w = (const float*)d_in[13];
    const float* h2mod_b = (const float*)d_in[14];
    const float* modU_w  = (const float*)d_in[15];
    const float* modU_b  = (const float*)d_in[16];
    float* out = (float*)d_out;

    const int scan_smem = 11264 * sizeof(float); // 45056 B
    cudaFuncSetAttribute(k_scan, cudaFuncAttributeMaxDynamicSharedMemorySize, scan_smem);

    k_xproj<<<dim3(4, 32), 256>>>(x, x2h_v, x2h_g, x2h_b);
    k_scan<<<NBLK, 256, scan_smem>>>(h0, v0, dU0, te0, tE0, alpha,
                                     h2h_v, h2h_g, h2h_b,
                                     h2mod_w, h2mod_b, modU_w, modU_b, out);
}